// round 16
// baseline (speedup 1.0000x reference)
#include <cuda_runtime.h>
#include <cuda_fp16.h>
#include <math.h>
#include <stdint.h>
#include <string.h>

#define BB 2
#define NN 65536
#define DD 512
#define MM 128
#define HH 32
#define TILE_N 64
#define CHUNKS (NN / TILE_N)   /* 1024 per batch */
#define NT (BB * CHUNKS)       /* 2048 tiles */
#define NC (MM + HH)           /* 160  */
#define NXW 260                /* u32 words per s_nx row (256 + 4 pad) */
#define WW  20                 /* u32 words per s_w chunk row (16 + 4 pad) */
#define LSTR 164               /* logits smem row stride (160 + 4 pad) */
#define NTHREADS 512

/* Deterministic scratch (no device-side allocation). */
__device__ float    g_partials[BB * MM * CHUNKS];
__device__ uint32_t g_w[NC * 256];   /* packed fp16x2, [row][k/2] */

__device__ __forceinline__ uint32_t smem_u32(const void* p)
{
    uint32_t a;
    asm("{ .reg .u64 t; cvta.to.shared.u64 t, %1; cvt.u32.u64 %0, t; }"
        : "=r"(a) : "l"(p));
    return a;
}

__device__ __forceinline__ uint32_t packh(float a, float b)
{
    __half2 t;
    t.x = __float2half_rn(a);
    t.y = __float2half_rn(b);
    uint32_t r;
    memcpy(&r, &t, 4);
    return r;
}

__device__ __forceinline__ void mma_f16(float* c, const uint32_t* a, const uint32_t* b)
{
    asm volatile(
        "mma.sync.aligned.m16n8k16.row.col.f32.f16.f16.f32 "
        "{%0,%1,%2,%3}, {%4,%5,%6,%7}, {%8,%9}, {%0,%1,%2,%3};"
        : "+f"(c[0]), "+f"(c[1]), "+f"(c[2]), "+f"(c[3])
        : "r"(a[0]), "r"(a[1]), "r"(a[2]), "r"(a[3]), "r"(b[0]), "r"(b[1]));
}

__device__ __forceinline__ void cp16(uint32_t dst, const uint32_t* src)
{
    asm volatile("cp.async.cg.shared.global [%0], [%1], 16;"
                 :: "r"(dst), "l"(__cvta_generic_to_global(src)) : "memory");
}
#define CP_COMMIT() asm volatile("cp.async.commit_group;" ::: "memory")
#define CP_WAIT0()  asm volatile("cp.async.wait_group 0;" ::: "memory")

/* One-time W convert: fp32 -> fp16 packed pairs. */
__global__ void prep_w(const float* __restrict__ W_lin, const float* __restrict__ W_t1)
{
    const int idx = blockIdx.x * 256 + threadIdx.x;   /* 0 .. 160*256-1 */
    if (idx >= NC * 256) return;
    const int row = idx >> 8;
    const int w   = idx & 255;
    const float* src = (row < MM) ? (W_lin + (size_t)row * DD)
                                  : (W_t1 + (size_t)(row - MM) * DD);
    g_w[idx] = packh(src[2 * w], src[2 * w + 1]);
}

/* Async copy of W chunk kc (640 x 16B) into buffer buf. */
__device__ __forceinline__ void load_chunk_async(uint32_t wbase_u32, int kc, int buf, int tid)
{
    const uint32_t dbase = wbase_u32 + buf * (NC * WW * 4);
    #pragma unroll
    for (int s = 0; s < 2; s++) {
        const int idx = tid + s * NTHREADS;
        if (idx < 640) {
            const int row = idx >> 2;
            const int q   = idx & 3;
            cp16(dbase + (row * WW + q * 4) * 4, g_w + row * 256 + kc * 16 + q * 4);
        }
    }
    CP_COMMIT();
}

__global__ void __launch_bounds__(NTHREADS, 2)
fused_kernel(const float* __restrict__ x, const float* __restrict__ mass,
             const float* __restrict__ ln_g, const float* __restrict__ ln_b,
             const float* __restrict__ b_lin, const float* __restrict__ W_t2,
             const float* __restrict__ b_t2, float* __restrict__ out)
{
    extern __shared__ uint32_t smu[];
    uint32_t* s_nxh = smu;                   /* 64*260 = 16640 */
    uint32_t* s_wb  = smu + 16640;           /* 2 bufs x 160*20 = 6400 */
    float*    s_g   = (float*)(smu + 23040); /* 512 */
    float*    s_b   = s_g + DD;              /* 512 */
    float*    s_bl  = s_b + DD;              /* 128 */
    float*    s_w2  = s_bl + MM;             /* 32  */
    float*    s_ps  = s_w2 + HH;             /* 16*128 = 2048 */
    float*    s_log = (float*)smu;           /* aliases s_nx after GEMM */
    float*    s_stg = (float*)s_wb;          /* 32x65 floats, free post-GEMM */

    const uint32_t wbase_u32 = smem_u32(s_wb);

    const int tid  = threadIdx.x;
    const int lane = tid & 31;
    const int warp = tid >> 5;
    const int bid  = blockIdx.x;
    const int gdim = gridDim.x;
    const int nloop = (NT - 1 - bid) / gdim + 1;

    const int wRow = warp >> 2;
    const int wCol = warp & 3;
    const int grp  = lane >> 2;
    const int tig  = lane & 3;
    const int arow = wRow * 16 + grp;

    for (int i2 = tid; i2 < DD; i2 += NTHREADS) { s_g[i2] = ln_g[i2]; s_b[i2] = ln_b[i2]; }
    if (tid < MM) s_bl[tid] = b_lin[tid];
    if (tid < HH) s_w2[tid] = W_t2[tid];
    const float bt2 = b_t2[0];
    __syncthreads();

    /* Half-phase stagger: decorrelate the two co-resident CTA groups so one
       CTA's DRAM phases overlap the other's tensor phase (persistent grid:
       no wave boundaries to re-align them). One-time ~25k-cycle cost. */
    if (bid >= (gdim >> 1)) {
        const long long t0 = clock64();
        while (clock64() - t0 < 25000) { }
    }
    __syncthreads();

    for (int i = 0; i < nloop; i++) {
        const int tau   = bid + i * gdim;
        const int b     = tau >> 10;           /* /1024 */
        const int chunk = tau & (CHUNKS - 1);
        const int n0    = chunk * TILE_N;

        /* kick off W chunk 0 — hides under LN x loads */
        load_chunk_async(wbase_u32, 0, 0, tid);

        /* ------------ Phase A: LayerNorm -> packed fp16 ------------ */
        for (int r = warp; r < TILE_N; r += 16) {
            const float4* xr = reinterpret_cast<const float4*>(
                x + ((size_t)(b * NN + n0 + r)) * DD);
            float4 v[4];
            float s = 0.f, sq = 0.f;
            #pragma unroll
            for (int q = 0; q < 4; q++) {
                v[q] = xr[lane + 32 * q];
                s  += v[q].x + v[q].y + v[q].z + v[q].w;
                sq += v[q].x * v[q].x + v[q].y * v[q].y
                    + v[q].z * v[q].z + v[q].w * v[q].w;
            }
            #pragma unroll
            for (int o = 16; o > 0; o >>= 1) {
                s  += __shfl_xor_sync(0xffffffffu, s,  o);
                sq += __shfl_xor_sync(0xffffffffu, sq, o);
            }
            const float mu   = s * (1.0f / DD);
            const float var  = sq * (1.0f / DD) - mu * mu;
            const float rstd = rsqrtf(var + 1e-5f);
            #pragma unroll
            for (int q = 0; q < 4; q++) {
                const int k = (lane + 32 * q) * 4;
                float4 o4;
                o4.x = (v[q].x - mu) * rstd * s_g[k + 0] + s_b[k + 0];
                o4.y = (v[q].y - mu) * rstd * s_g[k + 1] + s_b[k + 1];
                o4.z = (v[q].z - mu) * rstd * s_g[k + 2] + s_b[k + 2];
                o4.w = (v[q].w - mu) * rstd * s_g[k + 3] + s_b[k + 3];
                uint2 hv;
                hv.x = packh(o4.x, o4.y); hv.y = packh(o4.z, o4.w);
                const int wofs = r * NXW + (lane + 32 * q) * 2;
                *reinterpret_cast<uint2*>(s_nxh + wofs) = hv;
            }
        }

        /* ------------ Phase B: fp16 m16n8k16 GEMM, pipelined ------------ */
        float acc[5][4];
        #pragma unroll
        for (int j = 0; j < 5; j++)
            #pragma unroll
            for (int q = 0; q < 4; q++) acc[j][q] = 0.f;

        const uint32_t* ah_base = s_nxh + arow * NXW + tig;

        CP_WAIT0();
        __syncthreads();     /* s_nx ready + chunk 0 visible */

        for (int kc = 0; kc < 16; kc++) {
            if (kc < 15) load_chunk_async(wbase_u32, kc + 1, (kc + 1) & 1, tid);

            const uint32_t* bh_buf = s_wb + (kc & 1) * (NC * WW);

            #pragma unroll
            for (int ks = 0; ks < 2; ks++) {
                const int ko = kc * 16 + ks * 8;
                uint32_t ah[4];
                const uint32_t* aph = ah_base + ko;
                ah[0] = aph[0]; ah[1] = aph[8 * NXW];
                ah[2] = aph[4]; ah[3] = aph[8 * NXW + 4];
                #pragma unroll
                for (int j = 0; j < 5; j++) {
                    const int brow = (wCol * 40 + j * 8 + grp) * WW + ks * 8 + tig;
                    uint32_t bh[2];
                    bh[0] = bh_buf[brow]; bh[1] = bh_buf[brow + 4];
                    mma_f16(acc[j], ah, bh);
                }
            }
            if (kc < 15) CP_WAIT0();
            __syncthreads();
        }

        /* write logits (+ b_lin) to smem (aliases s_nx, synced above) */
        #pragma unroll
        for (int j = 0; j < 5; j++) {
            const int r0 = arow;
            const int c0 = wCol * 40 + j * 8 + 2 * tig;
            const float bb0 = (c0     < MM) ? s_bl[c0]     : 0.f;
            const float bb1 = (c0 + 1 < MM) ? s_bl[c0 + 1] : 0.f;
            s_log[r0 * LSTR + c0]           = acc[j][0] + bb0;
            s_log[r0 * LSTR + c0 + 1]       = acc[j][1] + bb1;
            s_log[(r0 + 8) * LSTR + c0]     = acc[j][2] + bb0;
            s_log[(r0 + 8) * LSTR + c0 + 1] = acc[j][3] + bb1;
        }
        __syncthreads();

        /* ------------ Phase C/D: temperature + softmax ------------ */
        float4 ps4 = make_float4(0.f, 0.f, 0.f, 0.f);
        for (int r = warp; r < TILE_N; r += 16) {
            float* lr = s_log + r * LSTR;

            const float tval = lr[MM + lane];
            const float gl = 0.5f * tval * (1.0f + erff(tval * 0.7071067811865476f));
            float cacc = gl * s_w2[lane];
            #pragma unroll
            for (int o = 16; o > 0; o >>= 1)
                cacc += __shfl_xor_sync(0xffffffffu, cacc, o);
            const float z    = cacc + bt2;
            const float sp   = (z > 20.f) ? z : log1pf(__expf(z));
            const float tau_ = fminf(fmaxf(sp, 0.01f), 3.0f);
            const float itau = __fdividef(1.0f, tau_);
            const float ms   = mass[(size_t)b * NN + n0 + r];

            float4 l4 = *reinterpret_cast<float4*>(lr + lane * 4);
            l4.x *= itau; l4.y *= itau; l4.z *= itau; l4.w *= itau;
            float mx = fmaxf(fmaxf(l4.x, l4.y), fmaxf(l4.z, l4.w));
            #pragma unroll
            for (int o = 16; o > 0; o >>= 1)
                mx = fmaxf(mx, __shfl_xor_sync(0xffffffffu, mx, o));
            float4 e;
            e.x = __expf(l4.x - mx); e.y = __expf(l4.y - mx);
            e.z = __expf(l4.z - mx); e.w = __expf(l4.w - mx);
            float ssum = e.x + e.y + e.z + e.w;
            #pragma unroll
            for (int o = 16; o > 0; o >>= 1)
                ssum += __shfl_xor_sync(0xffffffffu, ssum, o);
            const float inv = __fdividef(1.0f, ssum);
            float4 p;
            p.x = e.x * inv; p.y = e.y * inv; p.z = e.z * inv; p.w = e.w * inv;

            __stcs(reinterpret_cast<float4*>(
                out + ((size_t)b * NN + n0 + r) * MM + lane * 4), p);

            float4 pm;
            pm.x = p.x * ms; pm.y = p.y * ms; pm.z = p.z * ms; pm.w = p.w * ms;
            *reinterpret_cast<float4*>(lr + lane * 4) = pm;
            ps4.x += pm.x; ps4.y += pm.y; ps4.z += pm.z; ps4.w += pm.w;
        }

        s_ps[warp * MM + lane * 4 + 0] = ps4.x;
        s_ps[warp * MM + lane * 4 + 1] = ps4.y;
        s_ps[warp * MM + lane * 4 + 2] = ps4.z;
        s_ps[warp * MM + lane * 4 + 3] = ps4.w;
        __syncthreads();

        if (tid < MM) {
            float t = 0.f;
            #pragma unroll
            for (int w = 0; w < 16; w++) t += s_ps[w * MM + tid];
            g_partials[((size_t)b * MM + tid) * CHUNKS + chunk] = t;
        }

        /* ------- Phase E: conflict-free staged transpose of trial_in_t ---- */
        const size_t off1 = (size_t)BB * NN * MM;
        for (int mb = 0; mb < 4; mb++) {
            __syncthreads();
            #pragma unroll
            for (int it = 0; it < (TILE_N * 32) / NTHREADS; it++) {
                const int idx  = it * NTHREADS + tid;
                const int nl   = idx >> 5;
                const int mloc = idx & 31;
                s_stg[mloc * 65 + nl] = s_log[nl * LSTR + mb * 32 + mloc];
            }
            __syncthreads();
            #pragma unroll
            for (int it = 0; it < (TILE_N * 32) / NTHREADS; it++) {
                const int idx  = it * NTHREADS + tid;
                const int mloc = idx >> 6;
                const int nl   = idx & 63;
                __stcs(out + off1 + ((size_t)b * MM + mb * 32 + mloc) * NN + n0 + nl,
                       s_stg[mloc * 65 + nl]);
            }
        }

        /* protect s_wb (aliases s_stg) and s_nx (aliases s_log) for next tile */
        __syncthreads();
    }
}

__global__ void norm_kernel(float* __restrict__ out)
{
    __shared__ float red[256];
    const int idx = blockIdx.x;   /* b*M + m */
    const int tid = threadIdx.x;
    const float* p = g_partials + (size_t)idx * CHUNKS;
    float s = 0.f;
    for (int k = tid; k < CHUNKS; k += 256) s += p[k];
    red[tid] = s;
    __syncthreads();
    for (int o = 128; o > 0; o >>= 1) {
        if (tid < o) red[tid] += red[tid + o];
        __syncthreads();
    }
    if (tid == 0)
        out[(size_t)2 * BB * NN * MM + idx] = 1.0f / (red[0] + 1e-6f);
}

extern "C" void kernel_launch(void* const* d_in, const int* in_sizes, int n_in,
                              void* d_out, int out_size)
{
    const float* x     = (const float*)d_in[0];
    const float* mass  = (const float*)d_in[1];
    const float* ln_g  = (const float*)d_in[2];
    const float* ln_b  = (const float*)d_in[3];
    const float* W_lin = (const float*)d_in[4];
    const float* b_lin = (const float*)d_in[5];
    const float* W_t1  = (const float*)d_in[6];
    const float* W_t2  = (const float*)d_in[7];
    const float* b_t2  = (const float*)d_in[8];
    float* out = (float*)d_out;

    prep_w<<<NC, 256>>>(W_lin, W_t1);

    int nsm = 148;
    cudaDeviceGetAttribute(&nsm, cudaDevAttrMultiProcessorCount, 0);

    const int smem_bytes = (23040 + DD + DD + MM + HH + 16 * 128) * 4;  /* ~105 KB */
    cudaFuncSetAttribute(fused_kernel,
                         cudaFuncAttributeMaxDynamicSharedMemorySize, smem_bytes);

    fused_kernel<<<2 * nsm, NTHREADS, smem_bytes>>>(
        x, mass, ln_g, ln_b, b_lin, W_t2, b_t2, out);
    norm_kernel<<<BB * MM, 256>>>(out);
}

// round 17
// speedup vs baseline: 1.0315x; 1.0315x over previous
#include <cuda_runtime.h>
#include <cuda_fp16.h>
#include <math.h>
#include <stdint.h>
#include <string.h>

#define BB 2
#define NN 65536
#define DD 512
#define MM 128
#define HH 32
#define TILE_N 64
#define CHUNKS (NN / TILE_N)   /* 1024 per batch */
#define NT (BB * CHUNKS)       /* 2048 tiles */
#define NC (MM + HH)           /* 160  */
#define NXW 260                /* u32 words per s_nx row (256 + 4 pad) */
#define WW  20                 /* u32 words per s_w chunk row (16 + 4 pad) */
#define LSTR 164               /* logits smem row stride (160 + 4 pad) */
#define NTHREADS 512

/* Deterministic scratch (no device-side allocation). */
__device__ float    g_partials[BB * MM * CHUNKS];
__device__ uint32_t g_w[NC * 256];   /* packed fp16x2, [row][k/2] */

__device__ __forceinline__ uint32_t smem_u32(const void* p)
{
    uint32_t a;
    asm("{ .reg .u64 t; cvta.to.shared.u64 t, %1; cvt.u32.u64 %0, t; }"
        : "=r"(a) : "l"(p));
    return a;
}

__device__ __forceinline__ uint32_t packh(float a, float b)
{
    __half2 t;
    t.x = __float2half_rn(a);
    t.y = __float2half_rn(b);
    uint32_t r;
    memcpy(&r, &t, 4);
    return r;
}

__device__ __forceinline__ void mma_f16(float* c, const uint32_t* a, const uint32_t* b)
{
    asm volatile(
        "mma.sync.aligned.m16n8k16.row.col.f32.f16.f16.f32 "
        "{%0,%1,%2,%3}, {%4,%5,%6,%7}, {%8,%9}, {%0,%1,%2,%3};"
        : "+f"(c[0]), "+f"(c[1]), "+f"(c[2]), "+f"(c[3])
        : "r"(a[0]), "r"(a[1]), "r"(a[2]), "r"(a[3]), "r"(b[0]), "r"(b[1]));
}

__device__ __forceinline__ void cp16(uint32_t dst, const uint32_t* src)
{
    asm volatile("cp.async.cg.shared.global [%0], [%1], 16;"
                 :: "r"(dst), "l"(__cvta_generic_to_global(src)) : "memory");
}
#define CP_COMMIT() asm volatile("cp.async.commit_group;" ::: "memory")
#define CP_WAIT0()  asm volatile("cp.async.wait_group 0;" ::: "memory")

__device__ __forceinline__ void l2_prefetch(const float* p)
{
    asm volatile("prefetch.global.L2 [%0];" :: "l"(p));
}

/* One-time W convert: fp32 -> fp16 packed pairs. */
__global__ void prep_w(const float* __restrict__ W_lin, const float* __restrict__ W_t1)
{
    const int idx = blockIdx.x * 256 + threadIdx.x;   /* 0 .. 160*256-1 */
    if (idx >= NC * 256) return;
    const int row = idx >> 8;
    const int w   = idx & 255;
    const float* src = (row < MM) ? (W_lin + (size_t)row * DD)
                                  : (W_t1 + (size_t)(row - MM) * DD);
    g_w[idx] = packh(src[2 * w], src[2 * w + 1]);
}

/* Async copy of W chunk kc (640 x 16B) into buffer buf. */
__device__ __forceinline__ void load_chunk_async(uint32_t wbase_u32, int kc, int buf, int tid)
{
    const uint32_t dbase = wbase_u32 + buf * (NC * WW * 4);
    #pragma unroll
    for (int s = 0; s < 2; s++) {
        const int idx = tid + s * NTHREADS;
        if (idx < 640) {
            const int row = idx >> 2;
            const int q   = idx & 3;
            cp16(dbase + (row * WW + q * 4) * 4, g_w + row * 256 + kc * 16 + q * 4);
        }
    }
    CP_COMMIT();
}

__global__ void __launch_bounds__(NTHREADS, 2)
fused_kernel(const float* __restrict__ x, const float* __restrict__ mass,
             const float* __restrict__ ln_g, const float* __restrict__ ln_b,
             const float* __restrict__ b_lin, const float* __restrict__ W_t2,
             const float* __restrict__ b_t2, float* __restrict__ out)
{
    extern __shared__ uint32_t smu[];
    uint32_t* s_nxh = smu;                   /* 64*260 = 16640 */
    uint32_t* s_wb  = smu + 16640;           /* 2 bufs x 160*20 = 6400 */
    float*    s_g   = (float*)(smu + 23040); /* 512 */
    float*    s_b   = s_g + DD;              /* 512 */
    float*    s_bl  = s_b + DD;              /* 128 */
    float*    s_w2  = s_bl + MM;             /* 32  */
    float*    s_ps  = s_w2 + HH;             /* 16*128 = 2048 */
    float*    s_log = (float*)smu;           /* aliases s_nx after GEMM */
    float*    s_stg = (float*)s_wb;          /* 32x65 floats, free post-GEMM */

    const uint32_t wbase_u32 = smem_u32(s_wb);

    const int tid  = threadIdx.x;
    const int lane = tid & 31;
    const int warp = tid >> 5;
    const int bid  = blockIdx.x;
    const int gdim = gridDim.x;
    const int nloop = (NT - 1 - bid) / gdim + 1;

    const int wRow = warp >> 2;
    const int wCol = warp & 3;
    const int grp  = lane >> 2;
    const int tig  = lane & 3;
    const int arow = wRow * 16 + grp;

    for (int i2 = tid; i2 < DD; i2 += NTHREADS) { s_g[i2] = ln_g[i2]; s_b[i2] = ln_b[i2]; }
    if (tid < MM) s_bl[tid] = b_lin[tid];
    if (tid < HH) s_w2[tid] = W_t2[tid];
    const float bt2 = b_t2[0];
    __syncthreads();

    for (int i = 0; i < nloop; i++) {
        const int tau   = bid + i * gdim;
        const int b     = tau >> 10;           /* /1024 */
        const int chunk = tau & (CHUNKS - 1);
        const int n0    = chunk * TILE_N;

        /* next tile's x base for L2 prefetch during GEMM */
        const int ntau = tau + gdim;
        const float* xnext = nullptr;
        if (ntau < NT)
            xnext = x + ((size_t)(ntau >> 10) * NN
                       + (size_t)(ntau & (CHUNKS - 1)) * TILE_N) * DD;

        /* kick off W chunk 0 — hides under LN x loads */
        load_chunk_async(wbase_u32, 0, 0, tid);

        /* ------------ Phase A: LayerNorm -> packed fp16 ------------ */
        for (int r = warp; r < TILE_N; r += 16) {
            const float4* xr = reinterpret_cast<const float4*>(
                x + ((size_t)(b * NN + n0 + r)) * DD);
            float4 v[4];
            float s = 0.f, sq = 0.f;
            #pragma unroll
            for (int q = 0; q < 4; q++) {
                v[q] = xr[lane + 32 * q];
                s  += v[q].x + v[q].y + v[q].z + v[q].w;
                sq += v[q].x * v[q].x + v[q].y * v[q].y
                    + v[q].z * v[q].z + v[q].w * v[q].w;
            }
            #pragma unroll
            for (int o = 16; o > 0; o >>= 1) {
                s  += __shfl_xor_sync(0xffffffffu, s,  o);
                sq += __shfl_xor_sync(0xffffffffu, sq, o);
            }
            const float mu   = s * (1.0f / DD);
            const float var  = sq * (1.0f / DD) - mu * mu;
            const float rstd = rsqrtf(var + 1e-5f);
            #pragma unroll
            for (int q = 0; q < 4; q++) {
                const int k = (lane + 32 * q) * 4;
                float4 o4;
                o4.x = (v[q].x - mu) * rstd * s_g[k + 0] + s_b[k + 0];
                o4.y = (v[q].y - mu) * rstd * s_g[k + 1] + s_b[k + 1];
                o4.z = (v[q].z - mu) * rstd * s_g[k + 2] + s_b[k + 2];
                o4.w = (v[q].w - mu) * rstd * s_g[k + 3] + s_b[k + 3];
                uint2 hv;
                hv.x = packh(o4.x, o4.y); hv.y = packh(o4.z, o4.w);
                const int wofs = r * NXW + (lane + 32 * q) * 2;
                *reinterpret_cast<uint2*>(s_nxh + wofs) = hv;
            }
        }

        /* ------------ Phase B: fp16 m16n8k16 GEMM, pipelined ------------ */
        float acc[5][4];
        #pragma unroll
        for (int j = 0; j < 5; j++)
            #pragma unroll
            for (int q = 0; q < 4; q++) acc[j][q] = 0.f;

        const uint32_t* ah_base = s_nxh + arow * NXW + tig;

        CP_WAIT0();
        __syncthreads();     /* s_nx ready + chunk 0 visible */

        for (int kc = 0; kc < 16; kc++) {
            if (kc < 15) load_chunk_async(wbase_u32, kc + 1, (kc + 1) & 1, tid);

            /* L2 prefetch of next tile's x: 64 lines (128B) per iteration,
               1024 lines total = the full 131 kB tile. DRAM transfer runs
               under this tile's tensor work; LN(t+1) then hits L2. */
            if (xnext && tid < 64)
                l2_prefetch(xnext + (kc * 64 + tid) * 32);

            const uint32_t* bh_buf = s_wb + (kc & 1) * (NC * WW);

            #pragma unroll
            for (int ks = 0; ks < 2; ks++) {
                const int ko = kc * 16 + ks * 8;
                uint32_t ah[4];
                const uint32_t* aph = ah_base + ko;
                ah[0] = aph[0]; ah[1] = aph[8 * NXW];
                ah[2] = aph[4]; ah[3] = aph[8 * NXW + 4];
                #pragma unroll
                for (int j = 0; j < 5; j++) {
                    const int brow = (wCol * 40 + j * 8 + grp) * WW + ks * 8 + tig;
                    uint32_t bh[2];
                    bh[0] = bh_buf[brow]; bh[1] = bh_buf[brow + 4];
                    mma_f16(acc[j], ah, bh);
                }
            }
            if (kc < 15) CP_WAIT0();
            __syncthreads();
        }

        /* write logits (+ b_lin) to smem (aliases s_nx, synced above) */
        #pragma unroll
        for (int j = 0; j < 5; j++) {
            const int r0 = arow;
            const int c0 = wCol * 40 + j * 8 + 2 * tig;
            const float bb0 = (c0     < MM) ? s_bl[c0]     : 0.f;
            const float bb1 = (c0 + 1 < MM) ? s_bl[c0 + 1] : 0.f;
            s_log[r0 * LSTR + c0]           = acc[j][0] + bb0;
            s_log[r0 * LSTR + c0 + 1]       = acc[j][1] + bb1;
            s_log[(r0 + 8) * LSTR + c0]     = acc[j][2] + bb0;
            s_log[(r0 + 8) * LSTR + c0 + 1] = acc[j][3] + bb1;
        }
        __syncthreads();

        /* ------------ Phase C/D: temperature + softmax ------------ */
        float4 ps4 = make_float4(0.f, 0.f, 0.f, 0.f);
        for (int r = warp; r < TILE_N; r += 16) {
            float* lr = s_log + r * LSTR;

            const float tval = lr[MM + lane];
            const float gl = 0.5f * tval * (1.0f + erff(tval * 0.7071067811865476f));
            float cacc = gl * s_w2[lane];
            #pragma unroll
            for (int o = 16; o > 0; o >>= 1)
                cacc += __shfl_xor_sync(0xffffffffu, cacc, o);
            const float z    = cacc + bt2;
            const float sp   = (z > 20.f) ? z : log1pf(__expf(z));
            const float tau_ = fminf(fmaxf(sp, 0.01f), 3.0f);
            const float itau = __fdividef(1.0f, tau_);
            const float ms   = mass[(size_t)b * NN + n0 + r];

            float4 l4 = *reinterpret_cast<float4*>(lr + lane * 4);
            l4.x *= itau; l4.y *= itau; l4.z *= itau; l4.w *= itau;
            float mx = fmaxf(fmaxf(l4.x, l4.y), fmaxf(l4.z, l4.w));
            #pragma unroll
            for (int o = 16; o > 0; o >>= 1)
                mx = fmaxf(mx, __shfl_xor_sync(0xffffffffu, mx, o));
            float4 e;
            e.x = __expf(l4.x - mx); e.y = __expf(l4.y - mx);
            e.z = __expf(l4.z - mx); e.w = __expf(l4.w - mx);
            float ssum = e.x + e.y + e.z + e.w;
            #pragma unroll
            for (int o = 16; o > 0; o >>= 1)
                ssum += __shfl_xor_sync(0xffffffffu, ssum, o);
            const float inv = __fdividef(1.0f, ssum);
            float4 p;
            p.x = e.x * inv; p.y = e.y * inv; p.z = e.z * inv; p.w = e.w * inv;

            __stcs(reinterpret_cast<float4*>(
                out + ((size_t)b * NN + n0 + r) * MM + lane * 4), p);

            float4 pm;
            pm.x = p.x * ms; pm.y = p.y * ms; pm.z = p.z * ms; pm.w = p.w * ms;
            *reinterpret_cast<float4*>(lr + lane * 4) = pm;
            ps4.x += pm.x; ps4.y += pm.y; ps4.z += pm.z; ps4.w += pm.w;
        }

        s_ps[warp * MM + lane * 4 + 0] = ps4.x;
        s_ps[warp * MM + lane * 4 + 1] = ps4.y;
        s_ps[warp * MM + lane * 4 + 2] = ps4.z;
        s_ps[warp * MM + lane * 4 + 3] = ps4.w;
        __syncthreads();

        if (tid < MM) {
            float t = 0.f;
            #pragma unroll
            for (int w = 0; w < 16; w++) t += s_ps[w * MM + tid];
            g_partials[((size_t)b * MM + tid) * CHUNKS + chunk] = t;
        }

        /* ------- Phase E: conflict-free staged transpose of trial_in_t ---- */
        const size_t off1 = (size_t)BB * NN * MM;
        for (int mb = 0; mb < 4; mb++) {
            __syncthreads();
            #pragma unroll
            for (int it = 0; it < (TILE_N * 32) / NTHREADS; it++) {
                const int idx  = it * NTHREADS + tid;
                const int nl   = idx >> 5;
                const int mloc = idx & 31;
                s_stg[mloc * 65 + nl] = s_log[nl * LSTR + mb * 32 + mloc];
            }
            __syncthreads();
            #pragma unroll
            for (int it = 0; it < (TILE_N * 32) / NTHREADS; it++) {
                const int idx  = it * NTHREADS + tid;
                const int mloc = idx >> 6;
                const int nl   = idx & 63;
                __stcs(out + off1 + ((size_t)b * MM + mb * 32 + mloc) * NN + n0 + nl,
                       s_stg[mloc * 65 + nl]);
            }
        }

        /* protect s_wb (aliases s_stg) and s_nx (aliases s_log) for next tile */
        __syncthreads();
    }
}

__global__ void norm_kernel(float* __restrict__ out)
{
    __shared__ float red[256];
    const int idx = blockIdx.x;   /* b*M + m */
    const int tid = threadIdx.x;
    const float* p = g_partials + (size_t)idx * CHUNKS;
    float s = 0.f;
    for (int k = tid; k < CHUNKS; k += 256) s += p[k];
    red[tid] = s;
    __syncthreads();
    for (int o = 128; o > 0; o >>= 1) {
        if (tid < o) red[tid] += red[tid + o];
        __syncthreads();
    }
    if (tid == 0)
        out[(size_t)2 * BB * NN * MM + idx] = 1.0f / (red[0] + 1e-6f);
}

extern "C" void kernel_launch(void* const* d_in, const int* in_sizes, int n_in,
                              void* d_out, int out_size)
{
    const float* x     = (const float*)d_in[0];
    const float* mass  = (const float*)d_in[1];
    const float* ln_g  = (const float*)d_in[2];
    const float* ln_b  = (const float*)d_in[3];
    const float* W_lin = (const float*)d_in[4];
    const float* b_lin = (const float*)d_in[5];
    const float* W_t1  = (const float*)d_in[6];
    const float* W_t2  = (const float*)d_in[7];
    const float* b_t2  = (const float*)d_in[8];
    float* out = (float*)d_out;

    prep_w<<<NC, 256>>>(W_lin, W_t1);

    int nsm = 148;
    cudaDeviceGetAttribute(&nsm, cudaDevAttrMultiProcessorCount, 0);

    const int smem_bytes = (23040 + DD + DD + MM + HH + 16 * 128) * 4;  /* ~105 KB */
    cudaFuncSetAttribute(fused_kernel,
                         cudaFuncAttributeMaxDynamicSharedMemorySize, smem_bytes);

    fused_kernel<<<2 * nsm, NTHREADS, smem_bytes>>>(
        x, mass, ln_g, ln_b, b_lin, W_t2, b_t2, out);
    norm_kernel<<<BB * MM, 256>>>(out);
}